// round 7
// baseline (speedup 1.0000x reference)
#include <cuda_runtime.h>

#define NN 8192
#define B 256                    // time buckets
#define K1T 1024
#define NSEC 32                  // K1 sections = warps
#define SECW (NN / NSEC)         // 256 elems per section
#define MPT (SECW / 32)          // 8 elems per thread

#define GRID 296                 // 148 SMs * 2 CTAs
#define K2T 512
#define ROWS_CAP 28

// ---- device scratch (zero device-side allocation) ----
__device__ float4 g_tsort4[NN / 4];    // times, bucket-sorted
__device__ float4 g_psort4[NN / 4];    // preds, same order
__device__ float  g_row_t[NN];         // active rows (bucket-sorted)
__device__ float  g_row_c[NN];         // 1 + p[i]
__device__ int    g_row_sfx[NN];       // bstart[b+1]
__device__ int    g_row_bks[NN];       // bstart[b]
__device__ int    g_M;
__device__ float  g_regsum;
__device__ float  g_rank[GRID];
__device__ int    g_cnt[GRID];
__device__ unsigned g_ticket;          // zero-init; reset by last block

// ===================== Kernel 1: bucketize (stable) + regression =====================
__global__ void __launch_bounds__(K1T)
svm_prep_kernel(const float* __restrict__ pred,
                const float* __restrict__ target)
{
    extern __shared__ int s1[];
    int*   histJ  = s1;                    // [NSEC][B] counts -> running offsets
    int*   histA  = s1 + NSEC * B;         // [NSEC][B] active counts -> offsets
    int*   gst    = s1 + 2 * NSEC * B;     // [B+1] bucket starts (all elems)
    int*   ast    = gst + (B + 1);         // [B+1] bucket starts (actives)
    int*   scan   = ast + (B + 1);         // [B] scan buffer
    float* regred = (float*)(scan + B);    // [K1T]

    const int tid  = threadIdx.x;
    const int w    = tid >> 5;
    const int lane = tid & 31;
    const unsigned lt = (1u << lane) - 1u;

    for (int k = tid; k < 2 * NSEC * B; k += K1T) s1[k] = 0;
    __syncthreads();

    // Phase A: load, bucket, histogram (int atomics: order-free), regression.
    float tA[MPT], pA[MPT];
    int   bA[MPT];
    bool  aA[MPT];
    float regacc = 0.f;
    const int base = w * SECW;
    #pragma unroll
    for (int m = 0; m < MPT; ++m) {
        const int i = base + m * 32 + lane;
        const float2 te = ((const float2*)target)[i];   // (time, event)
        const float p = pred[i];
        int b = (int)(te.x * (B / 100.0f));             // monotone bucketing
        b = b < 0 ? 0 : (b > B - 1 ? B - 1 : b);
        atomicAdd(&histJ[w * B + b], 1);
        const bool act = (te.y != 0.f);
        if (act) atomicAdd(&histA[w * B + b], 1);
        tA[m] = te.x; pA[m] = p; bA[m] = b; aA[m] = act;
        float d = p - te.x;
        if (te.y == 0.f) d = fmaxf(d, 0.f);
        regacc = fmaf(d, d, regacc);
    }
    __syncthreads();

    // Phase B1: bucket totals + exclusive starts (all elems).
    if (tid < B) { int tot = 0; for (int s = 0; s < NSEC; ++s) tot += histJ[s * B + tid]; scan[tid] = tot; }
    __syncthreads();
    for (int off = 1; off < B; off <<= 1) {
        int v = 0;
        if (tid < B && tid >= off) v = scan[tid - off];
        __syncthreads();
        if (tid < B) scan[tid] += v;
        __syncthreads();
    }
    if (tid < B) gst[tid + 1] = scan[tid];
    if (tid == 0) gst[0] = 0;
    __syncthreads();
    if (tid < B) {                                       // rebase per-section to starts
        int run = gst[tid];
        for (int s = 0; s < NSEC; ++s) { int t0 = histJ[s * B + tid]; histJ[s * B + tid] = run; run += t0; }
    }
    __syncthreads();

    // Phase B2: same for actives.
    if (tid < B) { int tot = 0; for (int s = 0; s < NSEC; ++s) tot += histA[s * B + tid]; scan[tid] = tot; }
    __syncthreads();
    for (int off = 1; off < B; off <<= 1) {
        int v = 0;
        if (tid < B && tid >= off) v = scan[tid - off];
        __syncthreads();
        if (tid < B) scan[tid] += v;
        __syncthreads();
    }
    if (tid < B) ast[tid + 1] = scan[tid];
    if (tid == 0) ast[0] = 0;
    __syncthreads();
    if (tid < B) {
        int run = ast[tid];
        for (int s = 0; s < NSEC; ++s) { int t0 = histA[s * B + tid]; histA[s * B + tid] = run; run += t0; }
    }
    __syncthreads();

    // Phase C: stable scatter (section-ordered, iteration-ordered, lane-ordered).
    float* tsort = (float*)g_tsort4;
    float* psort = (float*)g_psort4;
    #pragma unroll
    for (int m = 0; m < MPT; ++m) {
        const int b = bA[m];
        const unsigned mm = __match_any_sync(0xffffffffu, b);
        const int ldr = __ffs(mm) - 1;
        const int rk  = __popc(mm & lt);
        int old = 0;
        if (lane == ldr) old = atomicAdd(&histJ[w * B + b], __popc(mm));
        old = __shfl_sync(0xffffffffu, old, ldr);
        const int pos = old + rk;
        tsort[pos] = tA[m];
        psort[pos] = pA[m];

        const unsigned am = __ballot_sync(0xffffffffu, aA[m]);
        if (aA[m]) {
            const unsigned mma = mm & am;
            const int ldra = __ffs(mma) - 1;
            const int rka  = __popc(mma & lt);
            int olda = 0;
            if (lane == ldra) olda = atomicAdd(&histA[w * B + b], __popc(mma));
            olda = __shfl_sync(am, olda, ldra);
            const int apos = olda + rka;
            g_row_t[apos]   = tA[m];
            g_row_c[apos]   = 1.0f + pA[m];
            g_row_sfx[apos] = gst[b + 1];
            g_row_bks[apos] = gst[b];
        }
    }

    // Phase D: regression reduction + M.
    regred[tid] = regacc;
    __syncthreads();
    for (int s = K1T / 2; s > 0; s >>= 1) {
        if (tid < s) regred[tid] += regred[tid + s];
        __syncthreads();
    }
    if (tid == 0) { g_regsum = regred[0]; g_M = ast[B]; }
}

// ===================== Kernel 2: suffix ranking + final combine =====================
__device__ __forceinline__ void proc_chunk(
    int cb, const float (&tt)[4], const float (&pp)[4],
    float& acc, int& cnt, float ti, float cc, int sfx, int bkt, int lane)
{
    if (cb + 128 <= bkt) return;                 // entire chunk has t_j < t_i
    if (cb >= sfx) {                             // entire chunk has t_j > t_i: clean
        #pragma unroll
        for (int k = 0; k < 4; ++k) {
            const float d = cc - pp[k];
            const float h = fmaxf(d, 0.f);
            acc = fmaf(h, h, acc);
        }
    } else {                                     // straddles row's bucket: compare
        const int dd = sfx - (cb + 4 * lane);    // count only j < sfx (rest analytic)
        #pragma unroll
        for (int k = 0; k < 4; ++k) {
            const bool q = tt[k] > ti;
            const float d = cc - pp[k];
            const float h = fmaxf(d, 0.f);
            if (q) acc = fmaf(h, h, acc);
            if (q & (k < dd)) cnt++;
        }
    }
}

__global__ void __launch_bounds__(K2T, 2)
svm_rank_kernel(float* __restrict__ out)
{
    const int tid  = threadIdx.x;
    const int w    = tid >> 5;
    const int lane = tid & 31;
    const int bid  = blockIdx.x;

    // 4 mirrored 128-wide chunks per warp (position sums constant -> balanced).
    const int cb0 = 256 * w;
    const int cb1 = 256 * w + 128;
    const int cb2 = 7936 - 256 * w;
    const int cb3 = 8064 - 256 * w;

    float tr[4][4], pr[4][4];
    {
        const int cbs[4] = {cb0, cb1, cb2, cb3};
        #pragma unroll
        for (int c = 0; c < 4; ++c) {
            const float4 tv = g_tsort4[(cbs[c] >> 2) + lane];
            const float4 pv = g_psort4[(cbs[c] >> 2) + lane];
            tr[c][0] = tv.x; tr[c][1] = tv.y; tr[c][2] = tv.z; tr[c][3] = tv.w;
            pr[c][0] = pv.x; pr[c][1] = pv.y; pr[c][2] = pv.z; pr[c][3] = pv.w;
        }
    }

    const int M = g_M;

    // Mirrored row pairs (k*2G+bid, k*2G+2G-1-bid): balanced suffix totals.
    __shared__ float s_rt[ROWS_CAP], s_rc[ROWS_CAP];
    __shared__ int   s_sfx[ROWS_CAP], s_bkt[ROWS_CAP];
    if (tid < ROWS_CAP) {
        const int k = tid >> 1;
        const int idx = 2 * GRID * k + ((tid & 1) ? (2 * GRID - 1 - bid) : bid);
        if (idx < M) {
            s_rt[tid]  = g_row_t[idx];
            s_rc[tid]  = g_row_c[idx];
            s_sfx[tid] = g_row_sfx[idx];
            s_bkt[tid] = g_row_bks[idx];
        }
    }
    __syncthreads();
    int nrows = 0;
    for (int r = 0; r < ROWS_CAP; ++r) {
        const int k = r >> 1;
        const int idx = 2 * GRID * k + ((r & 1) ? (2 * GRID - 1 - bid) : bid);
        nrows += (idx < M);
    }

    float a0 = 0.f, a1 = 0.f, a2 = 0.f, a3 = 0.f;
    int cnt = 0;
    for (int r = 0; r < nrows; ++r) {
        const float ti = s_rt[r];
        const float cc = s_rc[r];
        const int sfx = s_sfx[r];
        const int bkt = s_bkt[r];
        if (tid == 0) cnt += NN - sfx;           // analytic suffix count
        proc_chunk(cb0, tr[0], pr[0], a0, cnt, ti, cc, sfx, bkt, lane);
        proc_chunk(cb1, tr[1], pr[1], a1, cnt, ti, cc, sfx, bkt, lane);
        proc_chunk(cb2, tr[2], pr[2], a2, cnt, ti, cc, sfx, bkt, lane);
        proc_chunk(cb3, tr[3], pr[3], a3, cnt, ti, cc, sfx, bkt, lane);
    }
    const float rank_acc = (a0 + a1) + (a2 + a3);

    // Block reduction (deterministic tree).
    __shared__ float red_r[K2T];
    __shared__ int   red_c[K2T];
    red_r[tid] = rank_acc;
    red_c[tid] = cnt;
    __syncthreads();
    #pragma unroll
    for (int s = K2T / 2; s > 0; s >>= 1) {
        if (tid < s) {
            red_r[tid] += red_r[tid + s];
            red_c[tid] += red_c[tid + s];
        }
        __syncthreads();
    }

    __shared__ bool s_last;
    if (tid == 0) {
        g_rank[bid] = red_r[0];
        g_cnt[bid]  = red_c[0];
        __threadfence();
        const unsigned old = atomicAdd(&g_ticket, 1u);
        s_last = (old == GRID - 1);
    }
    __syncthreads();

    if (s_last) {
        __threadfence();
        __shared__ double sr[K2T];
        __shared__ double sc[K2T];
        double rank = 0.0, c = 0.0;
        if (tid < GRID) {
            rank = (double)g_rank[tid];
            c    = (double)g_cnt[tid];
        }
        sr[tid] = rank; sc[tid] = c;
        __syncthreads();
        #pragma unroll
        for (int s = K2T / 2; s > 0; s >>= 1) {
            if (tid < s) { sr[tid] += sr[tid + s]; sc[tid] += sc[tid + s]; }
            __syncthreads();
        }
        if (tid == 0) {
            double cc = sc[0];
            if (cc < 1.0) cc = 1.0;
            const double R = 0.5;
            const double loss = R * (sr[0] / cc)
                              + (1.0 - R) * ((double)g_regsum / (double)NN);
            out[0] = (float)loss;
            g_ticket = 0;                        // reset for next replay
        }
    }
}

extern "C" void kernel_launch(void* const* d_in, const int* in_sizes, int n_in,
                              void* d_out, int out_size)
{
    // Robust input mapping: pred has NN elements, target has 2*NN.
    int pred_idx = 0, tgt_idx = 1;
    if (n_in >= 2 && in_sizes[0] > in_sizes[1]) { pred_idx = 1; tgt_idx = 0; }
    const float* pred   = (const float*)d_in[pred_idx];
    const float* target = (const float*)d_in[tgt_idx];
    float* out = (float*)d_out;

    const int shmem1 = (2 * NSEC * B + 2 * (B + 1) + B) * sizeof(int)
                     + K1T * sizeof(float);     // ~72.7 KB
    cudaFuncSetAttribute(svm_prep_kernel,
                         cudaFuncAttributeMaxDynamicSharedMemorySize, shmem1);

    svm_prep_kernel<<<1, K1T, shmem1>>>(pred, target);
    svm_rank_kernel<<<GRID, K2T>>>(out);
}

// round 9
// speedup vs baseline: 1.3513x; 1.3513x over previous
#include <cuda_runtime.h>

#define NN 8192
#define B 128                    // time buckets (monotone bucketing)
#define PB 64                    // prep blocks
#define PT 128                   // prep threads (1 element each)
#define GRID 296                 // 148 SMs * 2 CTAs
#define K2T 512
#define ROWS_CAP 28              // covers M up to 8192 with mirrored pairs

// ---- device scratch (no allocation) ----
__device__ int    g_histT[B][PB];   // per-(bucket,block) counts, all elems
__device__ int    g_histA[B][PB];   // same, active (event==1) elems
__device__ float  g_regp[PB];       // per-block regression partials
__device__ float  g_ts[NN];         // times, bucket-sorted (stable)
__device__ float  g_ps[NN];         // preds, same order
__device__ float4 g_row4[NN];       // active rows: (t_i, 1+p_i, bits(sfx), bits(bkt))
__device__ int    g_M;
__device__ float  g_rank[GRID];
__device__ int    g_cnt[GRID];
__device__ unsigned g_bar1;         // prep phase barrier (reset by rank's last block)
__device__ unsigned g_ticket;       // rank completion ticket (reset likewise)

// ===================== Kernel 1: parallel deterministic bucketize =====================
__global__ void __launch_bounds__(PT)
svm_prep(const float* __restrict__ pred,
         const float* __restrict__ target)
{
    const int tid = threadIdx.x;
    const int bid = blockIdx.x;
    const int i   = bid * PT + tid;          // 64*128 = 8192

    const float t = target[2 * i];
    const float e = target[2 * i + 1];
    const float p = pred[i];
    int b = (int)(t * (B / 100.0f));         // monotone in t (fp mul by +const)
    b = b < 0 ? 0 : (b > B - 1 ? B - 1 : b);
    const bool act = (e != 0.f);

    __shared__ int s_h[B], s_ha[B];
    __shared__ int s_bkt[PT];
    __shared__ unsigned char s_act[PT];
    s_h[tid] = 0; s_ha[tid] = 0;             // PT == B
    s_bkt[tid] = b; s_act[tid] = act ? 1 : 0;
    __syncthreads();
    atomicAdd(&s_h[b], 1);
    if (act) atomicAdd(&s_ha[b], 1);

    // Regression partial (exact reduction tree).
    float d = p - t;
    if (!act) d = fmaxf(d, 0.f);
    __shared__ float s_reg[PT];
    s_reg[tid] = d * d;
    __syncthreads();
    #pragma unroll
    for (int s = PT / 2; s > 0; s >>= 1) {
        if (tid < s) s_reg[tid] += s_reg[tid + s];
        __syncthreads();
    }
    if (tid == 0) g_regp[bid] = s_reg[0];
    g_histT[tid][bid] = s_h[tid];
    g_histA[tid][bid] = s_ha[tid];
    __threadfence();
    __syncthreads();

    // Global arrival barrier (64 blocks, all resident -> safe).
    if (tid == 0) {
        atomicAdd(&g_bar1, 1u);
        while (*((volatile unsigned*)&g_bar1) < PB) { }
    }
    __syncthreads();
    __threadfence();

    // Phase 2 (redundant per block): totals, my-block offsets, exclusive starts.
    __shared__ int s_tot[B], s_my[B], s_tota[B], s_mya[B];
    {
        int tot = 0, my = 0, tota = 0, mya = 0;
        #pragma unroll 8
        for (int blk = 0; blk < PB; ++blk) {
            const int v  = g_histT[tid][blk];
            const int va = g_histA[tid][blk];
            tot += v; tota += va;
            if (blk < bid) { my += v; mya += va; }
        }
        s_tot[tid] = tot; s_my[tid] = my; s_tota[tid] = tota; s_mya[tid] = mya;
    }
    __syncthreads();
    __shared__ int s_sc[B], s_sca[B];        // inclusive scans
    s_sc[tid] = s_tot[tid]; s_sca[tid] = s_tota[tid];
    __syncthreads();
    #pragma unroll
    for (int off = 1; off < B; off <<= 1) {
        int v = 0, va = 0;
        if (tid >= off) { v = s_sc[tid - off]; va = s_sca[tid - off]; }
        __syncthreads();
        s_sc[tid] += v; s_sca[tid] += va;
        __syncthreads();
    }

    // Phase 3: stable scatter (block-slice order, index order within slice).
    int rank = 0, ranka = 0;
    for (int t2 = 0; t2 < tid; ++t2) {
        const bool same = (s_bkt[t2] == b);
        rank  += same ? 1 : 0;
        ranka += (same && s_act[t2]) ? 1 : 0;
    }
    const int gstb = s_sc[b] - s_tot[b];     // exclusive start, all elems
    const int pos  = gstb + s_my[b] + rank;
    g_ts[pos] = t;
    g_ps[pos] = p;
    if (act) {
        const int astb = s_sca[b] - s_tota[b];
        const int apos = astb + s_mya[b] + ranka;
        g_row4[apos] = make_float4(t, 1.0f + p,
                                   __int_as_float(s_sc[b]),   // sfx = gst[b+1]
                                   __int_as_float(gstb));     // bkt = gst[b]
    }
    if (bid == 0 && tid == 0) g_M = s_sca[B - 1];
}

// ===================== Kernel 2: suffix ranking + final combine =====================
__global__ void __launch_bounds__(K2T, 2)
svm_rank(float* __restrict__ out)
{
    const int tid  = threadIdx.x;
    const int bid  = blockIdx.x;
    const int w    = tid >> 5;
    const int lane = tid & 31;

    // Each warp owns two mirrored 256-elem chunks (balanced suffix work).
    const int loA = 256 * w;
    const int loB = 7936 - 256 * w;

    const float4* ts4 = (const float4*)g_ts;
    const float4* ps4 = (const float4*)g_ps;
    const float4 tA0 = ts4[(loA >> 2) + 2 * lane], tA1 = ts4[(loA >> 2) + 2 * lane + 1];
    const float4 pA0 = ps4[(loA >> 2) + 2 * lane], pA1 = ps4[(loA >> 2) + 2 * lane + 1];
    const float4 tB0 = ts4[(loB >> 2) + 2 * lane], tB1 = ts4[(loB >> 2) + 2 * lane + 1];
    const float4 pB0 = ps4[(loB >> 2) + 2 * lane], pB1 = ps4[(loB >> 2) + 2 * lane + 1];

    const int M = g_M;

    // Mirrored row pairing across blocks; inert rows marked sfx=bkt=NN.
    __shared__ float4 s_row[ROWS_CAP];
    if (tid < ROWS_CAP) {
        const int k = tid >> 1;
        const int idx = 2 * GRID * k + ((tid & 1) ? (2 * GRID - 1 - bid) : bid);
        s_row[tid] = (idx < M) ? g_row4[idx]
                   : make_float4(0.f, 0.f, __int_as_float(NN), __int_as_float(NN));
    }
    __syncthreads();

    float a0 = 0.f, a1 = 0.f, a2 = 0.f, a3 = 0.f;
    int cnt = 0;

#define CLEAN1(pv, acc) { const float h = fmaxf(cc - (pv), 0.f); acc = fmaf(h, h, acc); }
#define CMP1(tv, pv, kk, dd, acc) \
    { if ((tv) > ti) { const float h = fmaxf(cc - (pv), 0.f); acc = fmaf(h, h, acc); if ((kk) < (dd)) cnt++; } }

    #pragma unroll 1
    for (int r = 0; r < ROWS_CAP; ++r) {
        const float4 f = s_row[r];
        const float ti = f.x, cc = f.y;
        const int sfx = __float_as_int(f.z);
        const int bkt = __float_as_int(f.w);
        if (tid == 0) cnt += NN - sfx;               // analytic suffix count

        // chunk A
        if (bkt < loA + 256) {
            if (sfx <= loA) {
                CLEAN1(pA0.x, a0) CLEAN1(pA0.y, a1) CLEAN1(pA0.z, a0) CLEAN1(pA0.w, a1)
                CLEAN1(pA1.x, a0) CLEAN1(pA1.y, a1) CLEAN1(pA1.z, a0) CLEAN1(pA1.w, a1)
            } else {
                const int dd = sfx - (loA + 8 * lane);
                CMP1(tA0.x, pA0.x, 0, dd, a0) CMP1(tA0.y, pA0.y, 1, dd, a1)
                CMP1(tA0.z, pA0.z, 2, dd, a0) CMP1(tA0.w, pA0.w, 3, dd, a1)
                CMP1(tA1.x, pA1.x, 4, dd, a0) CMP1(tA1.y, pA1.y, 5, dd, a1)
                CMP1(tA1.z, pA1.z, 6, dd, a0) CMP1(tA1.w, pA1.w, 7, dd, a1)
            }
        }
        // chunk B
        if (bkt < loB + 256) {
            if (sfx <= loB) {
                CLEAN1(pB0.x, a2) CLEAN1(pB0.y, a3) CLEAN1(pB0.z, a2) CLEAN1(pB0.w, a3)
                CLEAN1(pB1.x, a2) CLEAN1(pB1.y, a3) CLEAN1(pB1.z, a2) CLEAN1(pB1.w, a3)
            } else {
                const int dd = sfx - (loB + 8 * lane);
                CMP1(tB0.x, pB0.x, 0, dd, a2) CMP1(tB0.y, pB0.y, 1, dd, a3)
                CMP1(tB0.z, pB0.z, 2, dd, a2) CMP1(tB0.w, pB0.w, 3, dd, a3)
                CMP1(tB1.x, pB1.x, 4, dd, a2) CMP1(tB1.y, pB1.y, 5, dd, a3)
                CMP1(tB1.z, pB1.z, 6, dd, a2) CMP1(tB1.w, pB1.w, 7, dd, a3)
            }
        }
    }
    const float rank_acc = (a0 + a1) + (a2 + a3);

    // Block reduction (deterministic tree).
    __shared__ float red_r[K2T];
    __shared__ int   red_c[K2T];
    red_r[tid] = rank_acc;
    red_c[tid] = cnt;
    __syncthreads();
    #pragma unroll
    for (int s = K2T / 2; s > 0; s >>= 1) {
        if (tid < s) { red_r[tid] += red_r[tid + s]; red_c[tid] += red_c[tid + s]; }
        __syncthreads();
    }

    __shared__ bool s_last;
    if (tid == 0) {
        g_rank[bid] = red_r[0];
        g_cnt[bid]  = red_c[0];
        __threadfence();
        const unsigned old = atomicAdd(&g_ticket, 1u);
        s_last = (old == GRID - 1);
    }
    __syncthreads();

    if (s_last) {
        __threadfence();
        __shared__ double sr[K2T], sc[K2T], sg[K2T];
        double rank = 0.0, c = 0.0, reg = 0.0;
        if (tid < GRID) { rank = (double)g_rank[tid]; c = (double)g_cnt[tid]; }
        if (tid < PB)   { reg  = (double)g_regp[tid]; }
        sr[tid] = rank; sc[tid] = c; sg[tid] = reg;
        __syncthreads();
        #pragma unroll
        for (int s = K2T / 2; s > 0; s >>= 1) {
            if (tid < s) { sr[tid] += sr[tid + s]; sc[tid] += sc[tid + s]; sg[tid] += sg[tid + s]; }
            __syncthreads();
        }
        if (tid == 0) {
            double cc = sc[0];
            if (cc < 1.0) cc = 1.0;
            const double R = 0.5;
            const double loss = R * (sr[0] / cc)
                              + (1.0 - R) * (sg[0] / (double)NN);
            out[0] = (float)loss;
            g_ticket = 0;             // reset for next graph replay
            g_bar1   = 0;
        }
    }
}

extern "C" void kernel_launch(void* const* d_in, const int* in_sizes, int n_in,
                              void* d_out, int out_size)
{
    // Robust input mapping: pred has NN elements, target has 2*NN.
    int pred_idx = 0, tgt_idx = 1;
    if (n_in >= 2 && in_sizes[0] > in_sizes[1]) { pred_idx = 1; tgt_idx = 0; }
    const float* pred   = (const float*)d_in[pred_idx];
    const float* target = (const float*)d_in[tgt_idx];
    float* out = (float*)d_out;

    svm_prep<<<PB, PT>>>(pred, target);
    svm_rank<<<GRID, K2T>>>(out);
}

// round 11
// speedup vs baseline: 1.7097x; 1.2653x over previous
#include <cuda_runtime.h>

#define NN 8192
#define B 128                    // time buckets (monotone bucketing)
#define PB 64                    // prep blocks (subset of GRID)
#define PTT 128                  // active prep threads per prep block
#define GRID 296                 // 148 SMs * 2 CTAs -> all resident
#define K2T 512
#define ROWS_CAP 28
#define RC2 (ROWS_CAP / 2)       // 14
#define G2 (2 * GRID)            // 592

// ---- device scratch (no allocation) ----
__device__ int    g_histT[B][PB];
__device__ int    g_histA[B][PB];
__device__ float  g_regp[PB];
__device__ float4 g_ts4[NN / 4];    // times, bucket-sorted
__device__ float4 g_ps4[NN / 4];    // preds, same order
__device__ float4 g_row4[NN];       // active rows: (t_i, 1+p_i, bits(sfx), bits(bkt))
__device__ int    g_M;
__device__ float  g_rank[GRID];
__device__ int    g_cnt[GRID];
__device__ volatile unsigned g_bar0;   // hist published (prep blocks)
__device__ volatile unsigned g_bar1;   // sort done (prep blocks)
__device__ unsigned g_ticket;          // rank completion

__global__ void __launch_bounds__(K2T, 2)
svm_fused(const float* __restrict__ pred,
          const float* __restrict__ target,
          float* __restrict__ out)
{
    const int tid  = threadIdx.x;
    const int bid  = blockIdx.x;
    const int w    = tid >> 5;
    const int lane = tid & 31;
    const unsigned lt = (1u << lane) - 1u;

    // =================== PREP (blocks 0..PB-1) ===================
    __shared__ int s_wh[4][B];       // per-warp bucket counts (all)
    __shared__ int s_wha[4][B];      // per-warp bucket counts (active)
    __shared__ int s_tot[B], s_my[B], s_tota[B], s_mya[B];
    __shared__ int s_sc[B], s_sca[B];
    __shared__ float s_reg[PTT];

    if (bid < PB) {                  // bid uniform: internal syncs legal
        if (tid < 4 * B)  { ((int*)s_wh)[tid] = 0; ((int*)s_wha)[tid] = 0; }
        __syncthreads();

        float tval = 0.f, pval = 0.f;
        int   myb = 0, lr = 0, lra = 0;
        bool  act = false;
        if (tid < PTT) {             // warps 0..3 fully active
            const int i = bid * PTT + tid;
            const float2 te = ((const float2*)target)[i];
            pval = pred[i];
            tval = te.x;
            int b = (int)(tval * (B / 100.0f));
            myb = b < 0 ? 0 : (b > B - 1 ? B - 1 : b);
            act = (te.y != 0.f);
            float d = pval - tval;
            if (!act) d = fmaxf(d, 0.f);
            s_reg[tid] = d * d;

            const unsigned mm = __match_any_sync(0xffffffffu, myb);
            lr = __popc(mm & lt);
            if (lane == (__ffs(mm) - 1)) s_wh[w][myb] = __popc(mm);
            const unsigned am = __ballot_sync(0xffffffffu, act);
            const unsigned mma = mm & am;
            lra = __popc(mma & lt);
            if (act && lane == (__ffs(mma) - 1)) s_wha[w][myb] = __popc(mma);
        }
        __syncthreads();

        if (tid < B) {               // publish per-block bucket totals
            const int h  = s_wh[0][tid] + s_wh[1][tid] + s_wh[2][tid] + s_wh[3][tid];
            const int ha = s_wha[0][tid] + s_wha[1][tid] + s_wha[2][tid] + s_wha[3][tid];
            g_histT[tid][bid] = h;
            g_histA[tid][bid] = ha;
        }
        // regression partial (tree over 128)
        #pragma unroll
        for (int s = PTT / 2; s > 0; s >>= 1) {
            __syncthreads();
            if (tid < s) s_reg[tid] += s_reg[tid + s];
        }
        __syncthreads();
        if (tid == 0) g_regp[bid] = s_reg[0];

        __threadfence();
        __syncthreads();
        if (tid == 0) {
            atomicAdd((unsigned*)&g_bar0, 1u);
            while (g_bar0 < PB) { }
        }
        __syncthreads();
        __threadfence();

        // totals + my-block offsets (row of 64 ints contiguous -> int4)
        if (tid < B) {
            int tot = 0, my = 0, tota = 0, mya = 0;
            const int4* rT = (const int4*)&g_histT[tid][0];
            const int4* rA = (const int4*)&g_histA[tid][0];
            #pragma unroll
            for (int q = 0; q < PB / 4; ++q) {
                const int4 v = rT[q], va = rA[q];
                const int blk = 4 * q;
                tot += v.x + v.y + v.z + v.w;
                tota += va.x + va.y + va.z + va.w;
                my  += (blk     < bid ? v.x : 0) + (blk + 1 < bid ? v.y : 0)
                     + (blk + 2 < bid ? v.z : 0) + (blk + 3 < bid ? v.w : 0);
                mya += (blk     < bid ? va.x : 0) + (blk + 1 < bid ? va.y : 0)
                     + (blk + 2 < bid ? va.z : 0) + (blk + 3 < bid ? va.w : 0);
            }
            s_tot[tid] = tot; s_my[tid] = my; s_tota[tid] = tota; s_mya[tid] = mya;
            s_sc[tid] = tot;  s_sca[tid] = tota;
        }
        __syncthreads();
        #pragma unroll
        for (int off = 1; off < B; off <<= 1) {   // inclusive scans
            int v = 0, va = 0;
            if (tid < B && tid >= off) { v = s_sc[tid - off]; va = s_sca[tid - off]; }
            __syncthreads();
            if (tid < B) { s_sc[tid] += v; s_sca[tid] += va; }
            __syncthreads();
        }

        // stable scatter
        if (tid < PTT) {
            const int b = myb;
            int cw = 0, cwa = 0;
            #pragma unroll
            for (int w2 = 0; w2 < 3; ++w2)
                if (w2 < w) { cw += s_wh[w2][b]; cwa += s_wha[w2][b]; }
            const int gstb = s_sc[b] - s_tot[b];
            const int pos  = gstb + s_my[b] + cw + lr;
            ((float*)g_ts4)[pos] = tval;
            ((float*)g_ps4)[pos] = pval;
            if (act) {
                const int apos = (s_sca[b] - s_tota[b]) + s_mya[b] + cwa + lra;
                g_row4[apos] = make_float4(tval, 1.0f + pval,
                                           __int_as_float(s_sc[b]),   // sfx
                                           __int_as_float(gstb));     // bkt
            }
        }
        if (bid == 0 && tid == 0) g_M = s_sca[B - 1];
        __threadfence();
        __syncthreads();
        if (tid == 0) atomicAdd((unsigned*)&g_bar1, 1u);
    }

    // =================== grid-wide wait for sorted data ===================
    if (tid == 0) { while (g_bar1 < PB) { } }
    __syncthreads();
    __threadfence();

    // =================== RANK (all blocks) ===================
    const int loA = 256 * w;
    const int loB = 7936 - 256 * w;
    const float4 tA0 = g_ts4[(loA >> 2) + 2 * lane], tA1 = g_ts4[(loA >> 2) + 2 * lane + 1];
    const float4 pA0 = g_ps4[(loA >> 2) + 2 * lane], pA1 = g_ps4[(loA >> 2) + 2 * lane + 1];
    const float4 tB0 = g_ts4[(loB >> 2) + 2 * lane], tB1 = g_ts4[(loB >> 2) + 2 * lane + 1];
    const float4 pB0 = g_ps4[(loB >> 2) + 2 * lane], pB1 = g_ps4[(loB >> 2) + 2 * lane + 1];

    const int M  = g_M;
    const int m0 = G2 - 1 - bid;
    const int E  = (M > bid) ? min(RC2, (M - bid + G2 - 1) / G2) : 0;
    const int O  = (M > m0)  ? min(RC2, (M - m0  + G2 - 1) / G2) : 0;
    const int nrows = E + O;

    __shared__ float4 s_row[ROWS_CAP];
    if (tid < ROWS_CAP) {
        const int k = tid >> 1;
        const bool odd = tid & 1;
        const int idx = G2 * k + (odd ? m0 : bid);
        if (idx < M) s_row[odd ? (E + k) : k] = g_row4[idx];
    }
    __syncthreads();

    float a0 = 0.f, a1 = 0.f, a2 = 0.f, a3 = 0.f;
    int cnt = 0;

#define CLEAN1(pv, acc) { const float h = fmaxf(cc - (pv), 0.f); acc = fmaf(h, h, acc); }
#define CMP1(tv, pv, kk, dd, acc) \
    { if ((tv) > ti) { const float h = fmaxf(cc - (pv), 0.f); acc = fmaf(h, h, acc); if ((kk) < (dd)) cnt++; } }

    float4 f = (nrows > 0) ? s_row[0] : make_float4(0.f, 0.f, 0.f, 0.f);
    #pragma unroll 1
    for (int r = 0; r < nrows; ++r) {
        const float4 fn = s_row[(r + 1 < nrows) ? r + 1 : r];   // prefetch
        const float ti = f.x, cc = f.y;
        const int sfx = __float_as_int(f.z);
        const int bkt = __float_as_int(f.w);
        if (tid == 0) cnt += NN - sfx;               // analytic suffix count

        if (bkt < loA + 256) {
            if (sfx <= loA) {
                CLEAN1(pA0.x, a0) CLEAN1(pA0.y, a1) CLEAN1(pA0.z, a0) CLEAN1(pA0.w, a1)
                CLEAN1(pA1.x, a0) CLEAN1(pA1.y, a1) CLEAN1(pA1.z, a0) CLEAN1(pA1.w, a1)
            } else {
                const int dd = sfx - (loA + 8 * lane);
                CMP1(tA0.x, pA0.x, 0, dd, a0) CMP1(tA0.y, pA0.y, 1, dd, a1)
                CMP1(tA0.z, pA0.z, 2, dd, a0) CMP1(tA0.w, pA0.w, 3, dd, a1)
                CMP1(tA1.x, pA1.x, 4, dd, a0) CMP1(tA1.y, pA1.y, 5, dd, a1)
                CMP1(tA1.z, pA1.z, 6, dd, a0) CMP1(tA1.w, pA1.w, 7, dd, a1)
            }
        }
        if (bkt < loB + 256) {
            if (sfx <= loB) {
                CLEAN1(pB0.x, a2) CLEAN1(pB0.y, a3) CLEAN1(pB0.z, a2) CLEAN1(pB0.w, a3)
                CLEAN1(pB1.x, a2) CLEAN1(pB1.y, a3) CLEAN1(pB1.z, a2) CLEAN1(pB1.w, a3)
            } else {
                const int dd = sfx - (loB + 8 * lane);
                CMP1(tB0.x, pB0.x, 0, dd, a2) CMP1(tB0.y, pB0.y, 1, dd, a3)
                CMP1(tB0.z, pB0.z, 2, dd, a2) CMP1(tB0.w, pB0.w, 3, dd, a3)
                CMP1(tB1.x, pB1.x, 4, dd, a2) CMP1(tB1.y, pB1.y, 5, dd, a3)
                CMP1(tB1.z, pB1.z, 6, dd, a2) CMP1(tB1.w, pB1.w, 7, dd, a3)
            }
        }
        f = fn;
    }
    const float rank_acc = (a0 + a1) + (a2 + a3);

    // block reduction (deterministic tree)
    __shared__ float red_r[K2T];
    __shared__ int   red_c[K2T];
    red_r[tid] = rank_acc;
    red_c[tid] = cnt;
    __syncthreads();
    #pragma unroll
    for (int s = K2T / 2; s > 0; s >>= 1) {
        if (tid < s) { red_r[tid] += red_r[tid + s]; red_c[tid] += red_c[tid + s]; }
        __syncthreads();
    }

    __shared__ bool s_last;
    if (tid == 0) {
        g_rank[bid] = red_r[0];
        g_cnt[bid]  = red_c[0];
        __threadfence();
        const unsigned old = atomicAdd(&g_ticket, 1u);
        s_last = (old == GRID - 1);
    }
    __syncthreads();

    if (s_last) {
        __threadfence();
        __shared__ double sr[K2T], sc[K2T], sg[K2T];
        double rank = 0.0, c = 0.0, reg = 0.0;
        if (tid < GRID) { rank = (double)g_rank[tid]; c = (double)g_cnt[tid]; }
        if (tid < PB)   { reg  = (double)g_regp[tid]; }
        sr[tid] = rank; sc[tid] = c; sg[tid] = reg;
        __syncthreads();
        #pragma unroll
        for (int s = K2T / 2; s > 0; s >>= 1) {
            if (tid < s) { sr[tid] += sr[tid + s]; sc[tid] += sc[tid + s]; sg[tid] += sg[tid + s]; }
            __syncthreads();
        }
        if (tid == 0) {
            double cc = sc[0];
            if (cc < 1.0) cc = 1.0;
            const double R = 0.5;
            out[0] = (float)(R * (sr[0] / cc) + (1.0 - R) * (sg[0] / (double)NN));
            g_ticket = 0;            // reset for next graph replay
            g_bar0 = 0;
            g_bar1 = 0;
        }
    }
}

extern "C" void kernel_launch(void* const* d_in, const int* in_sizes, int n_in,
                              void* d_out, int out_size)
{
    // Robust input mapping: pred has NN elements, target has 2*NN.
    int pred_idx = 0, tgt_idx = 1;
    if (n_in >= 2 && in_sizes[0] > in_sizes[1]) { pred_idx = 1; tgt_idx = 0; }
    const float* pred   = (const float*)d_in[pred_idx];
    const float* target = (const float*)d_in[tgt_idx];
    float* out = (float*)d_out;

    svm_fused<<<GRID, K2T>>>(pred, target, out);
}